// round 2
// baseline (speedup 1.0000x reference)
#include <cuda_runtime.h>

// Shape fixed by dataset: B=16, T=8192, N=32, depth=31.
constexpr int N_STACK = 32;
constexpr int DEPTH   = 31;
constexpr int TPB     = 256;
constexpr int PAD     = 257;                 // bank-conflict-free transpose pad
constexpr int CHUNK   = 8;                   // ops steps per smem chunk
constexpr int SGN_FLOATS = N_STACK * PAD;    // 8224
constexpr int OPS_FLOATS = (5 * CHUNK) * PAD;// 10280
constexpr int SMEM_BYTES = (SGN_FLOATS + OPS_FLOATS) * 4;  // 74016

__device__ __forceinline__ float clip_log(float l) {
    // tanh(l/10)*10 == 10*(t-1)/(t+1), t = e^{0.2 l}.  |l| <= ~30 at all call sites.
    float t = __expf(l * 0.2f);
    return 10.0f * __fdividef(t - 1.0f, t + 1.0f);
}

__global__ __launch_bounds__(TPB)
void stack_machine_kernel(const float* __restrict__ sgn,
                          const float* __restrict__ logm,
                          const float* __restrict__ ops,
                          float* __restrict__ out,
                          int bt_total) {
    extern __shared__ float sh[];
    float* SGNB = sh;                 // [32][PAD]  (persistent)
    float* OPSB = sh + SGN_FLOATS;    // [40][PAD]  (logm staging, then ops chunks)

    const int tid = threadIdx.x;
    const int blockBase = blockIdx.x * TPB;
    const int bt = blockBase + tid;

    // ---- Stage logm (into OPSB) and sgn (into SGNB), transposed, coalesced ----
    {
        const float* lsrc = logm + (size_t)blockBase * N_STACK;
        const float* ssrc = sgn  + (size_t)blockBase * N_STACK;
#pragma unroll
        for (int it = 0; it < N_STACK; it++) {
            int i = it * TPB + tid;          // coalesced global index
            int r = i >> 5, c = i & 31;      // r = row(thread), c = stack idx
            OPSB[c * PAD + r] = lsrc[i];
            SGNB[c * PAD + r] = ssrc[i];
        }
    }
    __syncthreads();

    // ---- Pull this thread's log row into registers, build prefix sum-of-squares ----
    float l[N_STACK];
#pragma unroll
    for (int c = 0; c < N_STACK; c++) l[c] = OPSB[c * PAD + tid];

    // At step k, prev_logs are the ORIGINAL values at indices 0..30-k (results
    // written at step j land at index 30-j and are consumed as `top` at step
    // j+1, never re-read below), so the RMS slice is a running suffix SS.
    float SS = 0.0f;
#pragma unroll
    for (int i = 0; i < N_STACK - 1; i++) SS = fmaf(l[i], l[i], SS);

    float rs = SGNB[(N_STACK - 1) * PAD + tid];  // running top sign
    float rl = l[N_STACK - 1];                   // running top log
    __syncthreads();  // logm staging dead; OPSB free for ops chunks

    const float* opsrc = ops + (size_t)blockBase * (DEPTH * 5);

#pragma unroll
    for (int ch = 0; ch < 4; ch++) {
        const int k0 = ch * CHUNK;
        const int NS = (ch < 3) ? CHUNK : (DEPTH - 3 * CHUNK);  // 8,8,8,7
        const int NF = 5 * NS;

        // Cooperative, ~coalesced chunk load, transposed into OPSB[j][t].
#pragma unroll
        for (int it = 0; it < NF; it++) {
            int i = it * TPB + tid;
            int t = i / NF;                  // NF is compile-time: fast div
            int j = i - t * NF;
            OPSB[j * PAD + t] = opsrc[(size_t)t * (DEPTH * 5) + k0 * 5 + j];
        }
        __syncthreads();

#pragma unroll
        for (int kk = 0; kk < NS; kk++) {
            const int k  = k0 + kk;
            const int si = N_STACK - 2 - k;          // sec = original input
            float ss = SGNB[si * PAD + tid];
            float sl = l[si];

            float p0 = OPSB[(kk * 5 + 0) * PAD + tid];
            float p1 = OPSB[(kk * 5 + 1) * PAD + tid];
            float p2 = OPSB[(kk * 5 + 2) * PAD + tid];
            float p3 = OPSB[(kk * 5 + 3) * PAD + tid];
            float p4 = OPSB[(kk * 5 + 4) * PAD + tid];

            // ---- shared magnitude math for add & sub (signs don't affect logs) ----
            float mx = fmaxf(sl, rl), mn = fminf(sl, rl);
            float lse = mx + __logf(1.0f + __expf(mn - mx));
            float C1  = clip_log(clip_log(lse));          // same-sign branch (double clip, as ref)
            float delta = fmaxf(fminf(mn - mx, -0.001f), -10.0f);
            float diff  = __logf(1.0f - __expf(delta));
            bool  zr    = (mn == mx);
            float nl    = zr ? 0.0f : (mx + diff);
            float C2    = clip_log(nl);                   // opposite-sign branch

            bool  bx   = (sl >= rl);                      // big is sec?
            float bsA  = bx ? ss : rs;                    // big sign for add (y=+rs)
            float bsS  = bx ? ss : -rs;                   // big sign for sub (y=-rs)
            bool  same = (ss * rs > 0.0f);

            float aS, aL, sS, sL;
            if (same) { aS = ss;                 aL = C1;  sS = zr ? 0.0f : bsS;  sL = C2; }
            else      { aS = zr ? 0.0f : bsA;    aL = C2;  sS = ss;               sL = C1; }

            // Rare zero-sign cases (exact-zero sign inputs) — bit-match reference.
            if (ss == 0.0f || rs == 0.0f) {
                if (ss != 0.0f)      { aS = ss;   aL = clip_log(sl); sS = ss;   sL = aL; }
                else if (rs != 0.0f) { aS = rs;   aL = clip_log(rl); sS = -rs;  sL = aL; }
                else                 { aS = 0.0f; aL = 0.0f;         sS = 0.0f; sL = 0.0f; }
            }

            float mdS  = ss * rs;                         // mul & div share sign
            float mulL = clip_log(sl + rl);
            float divL = clip_log(sl - rl);

            float nsgn = aS * p0 + sS * p1 + mdS * (p2 + p3) + ss * p4;
            float nlog = aL * p0 + sL * p1 + mulL * p2 + divL * p3 + sl * p4;

            // RMS rescale over [orig prefix (len 31-k), nlog]
            const float cs_inv = 1.0f / (float)(N_STACK - k);
            float msq   = fmaf(nlog, nlog, SS) * cs_inv + 1e-6f;
            float scale = fminf(10.0f * rsqrtf(msq), 1.0f);

            rl = nlog * scale;
            rs = nsgn;
            SS = fmaf(-sl, sl, SS);                       // drop sec from prefix
        }
        __syncthreads();
    }

    out[bt]            = rs;   // (sign, log) stacked -> (2, B*T)
    out[bt_total + bt] = rl;
}

extern "C" void kernel_launch(void* const* d_in, const int* in_sizes, int n_in,
                              void* d_out, int out_size) {
    const float* sgn  = (const float*)d_in[0];
    const float* logm = (const float*)d_in[1];
    const float* ops  = (const float*)d_in[2];
    float* out = (float*)d_out;

    cudaFuncSetAttribute(stack_machine_kernel,
                         cudaFuncAttributeMaxDynamicSharedMemorySize, SMEM_BYTES);

    int bt_total = out_size / 2;
    int blocks = (bt_total + TPB - 1) / TPB;
    stack_machine_kernel<<<blocks, TPB, SMEM_BYTES>>>(sgn, logm, ops, out, bt_total);
}